// round 7
// baseline (speedup 1.0000x reference)
#include <cuda_runtime.h>
#include <math.h>

#define Bsz 512
#define Tsz 512
#define Dsz 256
#define Hsz 200
#define G4  800

// ---------------- scratch (static device allocations) ----------------
__device__ float  g_pre[(size_t)Tsz * Bsz * G4];   // [t][b][800]  ~839 MB
__device__ float4 g_Wt[Hsz * Hsz];                 // [j][k] -> (i,f,g,o) weights
__device__ float  g_bsum[G4];                      // b_ih + b_hh
__device__ float  g_h[2][Bsz * Hsz];               // double-buffered hidden state
__device__ float  g_c[Bsz * Hsz];                  // cell state
__device__ float  g_part[Hsz * Bsz];               // per-(k,b) output partials

// ---------------- prep: zero states, fuse biases, transpose W_hh ----------------
__global__ __launch_bounds__(256) void prep_kernel(const float* __restrict__ W_hh,
                                                   const float* __restrict__ b_ih,
                                                   const float* __restrict__ b_hh) {
    int i = blockIdx.x * 256 + threadIdx.x;
    if (i < Bsz * Hsz) {
        g_c[i] = 0.f;
        g_h[0][i] = 0.f;
        g_h[1][i] = 0.f;
        g_part[i] = 0.f;          // g_part is also 200*512 elements
    }
    if (i < G4) g_bsum[i] = b_ih[i] + b_hh[i];
    if (i < Hsz * Hsz) {
        int j = i / Hsz;          // input-hidden index
        int k = i % Hsz;          // output-hidden index
        float* w = (float*)&g_Wt[i];
#pragma unroll
        for (int g = 0; g < 4; g++)
            w[g] = W_hh[(g * Hsz + k) * Hsz + j];
    }
}

// ---------------- pre-GEMM: pre[t][b][g] = x[b][t][:] . W_ih[g][:] + bsum[g] ----------------
// 128x128 tile, 256 threads, 8x8 micro-tile, K-step 16.
__global__ __launch_bounds__(256) void pre_gemm(const float* __restrict__ x,
                                                const float* __restrict__ W_ih) {
    __shared__ __align__(16) float As[16][132];
    __shared__ __align__(16) float Bs[16][132];
    int tid = threadIdx.x;
    int tx = tid & 15, ty = tid >> 4;
    int m0 = blockIdx.y * 128;   // flattened (b*512+t) row
    int n0 = blockIdx.x * 128;   // gate column

    float acc[8][8];
#pragma unroll
    for (int i = 0; i < 8; i++)
#pragma unroll
        for (int j = 0; j < 8; j++) acc[i][j] = 0.f;

    for (int k0 = 0; k0 < Dsz; k0 += 16) {
#pragma unroll
        for (int l = 0; l < 2; l++) {
            int flat = tid * 2 + l;          // 0..511
            int ml = flat >> 2;              // 0..127
            int kk = (flat & 3) << 2;
            float4 v = *(const float4*)&x[(size_t)(m0 + ml) * Dsz + k0 + kk];
            As[kk + 0][ml] = v.x; As[kk + 1][ml] = v.y;
            As[kk + 2][ml] = v.z; As[kk + 3][ml] = v.w;
            int g = n0 + ml;
            float4 w = make_float4(0.f, 0.f, 0.f, 0.f);
            if (g < G4) w = *(const float4*)&W_ih[(size_t)g * Dsz + k0 + kk];
            Bs[kk + 0][ml] = w.x; Bs[kk + 1][ml] = w.y;
            Bs[kk + 2][ml] = w.z; Bs[kk + 3][ml] = w.w;
        }
        __syncthreads();
#pragma unroll
        for (int kk = 0; kk < 16; kk++) {
            float4 a0 = *(const float4*)&As[kk][ty * 8];
            float4 a1 = *(const float4*)&As[kk][ty * 8 + 4];
            float4 b0 = *(const float4*)&Bs[kk][tx * 8];
            float4 b1 = *(const float4*)&Bs[kk][tx * 8 + 4];
            float a[8] = {a0.x, a0.y, a0.z, a0.w, a1.x, a1.y, a1.z, a1.w};
            float b[8] = {b0.x, b0.y, b0.z, b0.w, b1.x, b1.y, b1.z, b1.w};
#pragma unroll
            for (int i = 0; i < 8; i++)
#pragma unroll
                for (int j = 0; j < 8; j++)
                    acc[i][j] += a[i] * b[j];
        }
        __syncthreads();
    }
    // Store: m = b*512 + t -> pre laid out [t][b][g] for the step kernels.
#pragma unroll
    for (int i = 0; i < 8; i++) {
        int m = m0 + ty * 8 + i;
        int b = m >> 9;
        int t = m & 511;
        size_t base = ((size_t)t * Bsz + b) * G4;
#pragma unroll
        for (int j4 = 0; j4 < 2; j4++) {
            int g = n0 + tx * 8 + j4 * 4;
            if (g + 3 < G4) {
                float4 v;
                v.x = acc[i][j4 * 4 + 0] + g_bsum[g + 0];
                v.y = acc[i][j4 * 4 + 1] + g_bsum[g + 1];
                v.z = acc[i][j4 * 4 + 2] + g_bsum[g + 2];
                v.w = acc[i][j4 * 4 + 3] + g_bsum[g + 3];
                *(float4*)&g_pre[base + g] = v;
            }
        }
    }
}

// ---------------- one LSTM timestep ----------------
// Grid: (8 k-slices of 25, 16 batch-tiles of 32). Block owns (batch-tile x k-slice):
// computes all 4 gates for its cells -> full cell update locally, no cross-block deps.
__global__ __launch_bounds__(256) void lstm_step(const float* __restrict__ W_out,
                                                 int t, int parity) {
    __shared__ __align__(16) float hsf[32 * Hsz];     // h tile [b_local][j], 25.6 KB
    const float* __restrict__ h_prev = g_h[parity];
    float* __restrict__ h_next = g_h[parity ^ 1];
    int tid = threadIdx.x;
    int b0 = blockIdx.y * 32;
    int k0 = blockIdx.x * 25;

#pragma unroll
    for (int idx = tid; idx < 32 * Hsz; idx += 256)
        hsf[idx] = h_prev[b0 * Hsz + idx];
    __syncthreads();

    if (tid < 200) {
        int k_local = tid % 25;
        int b_grp = tid / 25;          // 0..7, each handles 4 batch rows
        int k = k0 + k_local;
        int bl = b_grp * 4;

        float acc[4][4];               // [gate][batch]
#pragma unroll
        for (int g = 0; g < 4; g++)
#pragma unroll
            for (int i = 0; i < 4; i++) acc[g][i] = 0.f;

        const float4* __restrict__ Wp = g_Wt;
#pragma unroll 2
        for (int j = 0; j < Hsz; j += 4) {
            float4 w0 = Wp[(j + 0) * Hsz + k];
            float4 w1 = Wp[(j + 1) * Hsz + k];
            float4 w2 = Wp[(j + 2) * Hsz + k];
            float4 w3 = Wp[(j + 3) * Hsz + k];
#pragma unroll
            for (int i = 0; i < 4; i++) {
                float4 hv = *(const float4*)&hsf[(bl + i) * Hsz + j];
                acc[0][i] += w0.x * hv.x + w1.x * hv.y + w2.x * hv.z + w3.x * hv.w;
                acc[1][i] += w0.y * hv.x + w1.y * hv.y + w2.y * hv.z + w3.y * hv.w;
                acc[2][i] += w0.z * hv.x + w1.z * hv.y + w2.z * hv.z + w3.z * hv.w;
                acc[3][i] += w0.w * hv.x + w1.w * hv.y + w2.w * hv.z + w3.w * hv.w;
            }
        }

        float wout = W_out[t * Hsz + k];
#pragma unroll
        for (int i = 0; i < 4; i++) {
            int b = b0 + bl + i;
            size_t pbase = ((size_t)t * Bsz + b) * G4 + k;
            float gi = acc[0][i] + g_pre[pbase];
            float gf = acc[1][i] + g_pre[pbase + 200];
            float gg = acc[2][i] + g_pre[pbase + 400];
            float go = acc[3][i] + g_pre[pbase + 600];
            gi = 1.f / (1.f + __expf(-gi));
            gf = 1.f / (1.f + __expf(-gf));
            gg = tanhf(gg);
            go = 1.f / (1.f + __expf(-go));
            int ck = b * Hsz + k;
            float c = gf * g_c[ck] + gi * gg;
            g_c[ck] = c;
            float h = go * tanhf(c);
            h_next[ck] = h;
            g_part[k * Bsz + b] += wout * h;   // owner-unique slot: deterministic
        }
    }
}

// ---------------- final reduction: out[b] = sum_k part[k][b] + b_out ----------------
__global__ __launch_bounds__(256) void finalize_kernel(const float* __restrict__ b_out,
                                                       float* __restrict__ out) {
    int b = blockIdx.x * 256 + threadIdx.x;
    if (b < Bsz) {
        float s = b_out[0];
#pragma unroll 8
        for (int k = 0; k < Hsz; k++)
            s += g_part[k * Bsz + b];
        out[b] = s;
    }
}

extern "C" void kernel_launch(void* const* d_in, const int* in_sizes, int n_in,
                              void* d_out, int out_size) {
    const float* x     = (const float*)d_in[0];
    const float* W_ih  = (const float*)d_in[1];
    const float* W_hh  = (const float*)d_in[2];
    const float* b_ih  = (const float*)d_in[3];
    const float* b_hh  = (const float*)d_in[4];
    const float* W_out = (const float*)d_in[5];
    const float* b_out = (const float*)d_in[6];
    float* out = (float*)d_out;

    prep_kernel<<<400, 256>>>(W_hh, b_ih, b_hh);
    pre_gemm<<<dim3(7, 2048), 256>>>(x, W_ih);
    for (int t = 0; t < Tsz; t++)
        lstm_step<<<dim3(8, 16), 256>>>(W_out, t, t & 1);
    finalize_kernel<<<2, 256>>>(b_out, out);
}

// round 11
// speedup vs baseline: 1.3774x; 1.3774x over previous
#include <cuda_runtime.h>
#include <math.h>

#define Bsz 512
#define Tsz 512
#define Dsz 256
#define Hsz 200
#define G4  800
#define NBLK 128          // 8 k-slices x 16 batch-tiles, 1 block/SM -> co-resident

// ---------------- scratch (static device allocations) ----------------
__device__ float  g_pre[(size_t)Tsz * Bsz * G4];   // [t][b][800]
__device__ float  g_bsum[G4];                      // b_ih + b_hh
__device__ float  g_h[2][Bsz * Hsz];               // double-buffered hidden state
__device__ float  g_part[Hsz * Bsz];               // per-(k,b) output partials
__device__ unsigned g_count;                       // grid barrier arrive counter
__device__ volatile unsigned g_gen;                // grid barrier generation

// ---------------- f32x2 helpers (FFMA2: 2 MACs per instruction) ----------------
__device__ __forceinline__ void ffma2(unsigned long long &d,
                                      unsigned long long a, unsigned long long b) {
    asm("fma.rn.f32x2 %0, %1, %2, %0;" : "+l"(d) : "l"(a), "l"(b));
}
__device__ __forceinline__ float pairsum(unsigned long long v) {
    float lo, hi;
    asm("mov.b64 {%0,%1}, %2;" : "=f"(lo), "=f"(hi) : "l"(v));
    return lo + hi;
}

// ---------------- prep: zero h, fuse biases, reset barrier ----------------
__global__ __launch_bounds__(256) void prep_kernel(const float* __restrict__ b_ih,
                                                   const float* __restrict__ b_hh) {
    int i = blockIdx.x * 256 + threadIdx.x;
    if (i < Bsz * Hsz) { g_h[0][i] = 0.f; g_h[1][i] = 0.f; }
    if (i < G4) g_bsum[i] = b_ih[i] + b_hh[i];
    if (i == 0) { g_count = 0u; g_gen = 0u; }
}

// ---------------- pre-GEMM (f32x2): pre[t][b][g] = x[b][t][:].W_ih[g][:] + bsum ----------------
// 128x128 tile, 256 threads, 8x8 micro-tile. Smem is k-PAIR major (float2 lanes)
// so every FMA is a packed fma.rn.f32x2: 64 FFMA2 per k-pair instead of 128 FFMA.
__global__ __launch_bounds__(256) void pre_gemm(const float* __restrict__ x,
                                                const float* __restrict__ W_ih) {
    __shared__ __align__(16) float2 As2[8][128];   // [k-pair][m] -> (x_k0, x_k1)
    __shared__ __align__(16) float2 Bs2[8][128];   // [k-pair][g]
    int tid = threadIdx.x;
    int tx = tid & 15, ty = tid >> 4;
    int m0 = blockIdx.y * 128;   // flattened (b*512+t) row
    int n0 = blockIdx.x * 128;   // gate column

    unsigned long long acc2[8][8];   // packed (even-k, odd-k) partial sums
#pragma unroll
    for (int i = 0; i < 8; i++)
#pragma unroll
        for (int j = 0; j < 8; j++) acc2[i][j] = 0ull;

    for (int k0 = 0; k0 < Dsz; k0 += 16) {
#pragma unroll
        for (int l = 0; l < 2; l++) {
            int flat = tid * 2 + l;          // 0..511
            int ml = flat >> 2;              // 0..127
            int kk = (flat & 3) << 2;        // 0,4,8,12
            int kp = kk >> 1;                // 0,2,4,6
            float4 v = *(const float4*)&x[(size_t)(m0 + ml) * Dsz + k0 + kk];
            As2[kp][ml]     = make_float2(v.x, v.y);
            As2[kp + 1][ml] = make_float2(v.z, v.w);
            int g = n0 + ml;
            float4 w = make_float4(0.f, 0.f, 0.f, 0.f);
            if (g < G4) w = *(const float4*)&W_ih[(size_t)g * Dsz + k0 + kk];
            Bs2[kp][ml]     = make_float2(w.x, w.y);
            Bs2[kp + 1][ml] = make_float2(w.z, w.w);
        }
        __syncthreads();
#pragma unroll
        for (int kp = 0; kp < 8; kp++) {
            unsigned long long a[8], b[8];
            const ulonglong2* ap = (const ulonglong2*)&As2[kp][ty * 8];
            const ulonglong2* bp = (const ulonglong2*)&Bs2[kp][tx * 8];
#pragma unroll
            for (int q = 0; q < 4; q++) {
                ulonglong2 av = ap[q]; a[q * 2] = av.x; a[q * 2 + 1] = av.y;
                ulonglong2 bv = bp[q]; b[q * 2] = bv.x; b[q * 2 + 1] = bv.y;
            }
#pragma unroll
            for (int i = 0; i < 8; i++)
#pragma unroll
                for (int j = 0; j < 8; j++)
                    ffma2(acc2[i][j], a[i], b[j]);
        }
        __syncthreads();
    }
#pragma unroll
    for (int i = 0; i < 8; i++) {
        int m = m0 + ty * 8 + i;
        int b = m >> 9;
        int t = m & 511;
        size_t base = ((size_t)t * Bsz + b) * G4;
#pragma unroll
        for (int j4 = 0; j4 < 2; j4++) {
            int g = n0 + tx * 8 + j4 * 4;
            if (g + 3 < G4) {
                float4 v;
                v.x = pairsum(acc2[i][j4 * 4 + 0]) + g_bsum[g + 0];
                v.y = pairsum(acc2[i][j4 * 4 + 1]) + g_bsum[g + 1];
                v.z = pairsum(acc2[i][j4 * 4 + 2]) + g_bsum[g + 2];
                v.w = pairsum(acc2[i][j4 * 4 + 3]) + g_bsum[g + 3];
                *(float4*)&g_pre[base + g] = v;
            }
        }
    }
}

// ---------------- persistent LSTM: all 512 steps in ONE launch ----------------
// Grid: (8 k-slices of 25, 16 batch-tiles of 32) = 128 blocks, 1/SM (co-resident).
// W_hh slice lives in smem for the whole run; c and W_out partials live in regs.
// h is exchanged through L2 (st.global / __ldcg) with an atomic grid barrier.
#define WQ_N (4 * 50 * 25)                 // float4 count: [g][jquad][k_local]
#define SMEM_BYTES (WQ_N * 16 + 32 * Hsz * 4)   // 80000 + 25600 = 105600

__global__ __launch_bounds__(256, 1) void lstm_persist(const float* __restrict__ W_hh,
                                                       const float* __restrict__ W_out) {
    extern __shared__ char smem[];
    float4* wq = (float4*)smem;                       // [g][q][k_local] -> (w4q..w4q+3)
    float*  hs = (float*)(smem + WQ_N * 16);          // [32 b_local][200 j]
    int tid = threadIdx.x;
    int k0 = blockIdx.x * 25;
    int b0 = blockIdx.y * 32;

    // Build weight tile once: wq[g][q][kl] = W_hh[g*200 + k0+kl][4q..4q+3]
    for (int idx = tid; idx < WQ_N; idx += 256) {
        int g  = idx / 1250;
        int r  = idx % 1250;
        int q  = r / 25;
        int kl = r % 25;
        wq[(g * 50 + q) * 25 + kl] =
            *(const float4*)&W_hh[(size_t)(g * Hsz + k0 + kl) * Hsz + q * 4];
    }

    int kl = tid % 25;
    int bg = tid / 25;          // 0..7 (tid<200), each owns 4 batch rows
    int k  = k0 + kl;
    int bl = bg * 4;
    bool active = (tid < 200);

    float creg[4] = {0.f, 0.f, 0.f, 0.f};     // cell state: registers, whole run
    float wacc[4] = {0.f, 0.f, 0.f, 0.f};     // sum_t W_out[t,k]*h[t,b,k]
    unsigned myGen = 0;
    __syncthreads();                           // wq ready

    for (int t = 0; t < Tsz; t++) {
        const float* __restrict__ h_prev = g_h[t & 1];
        float* __restrict__ h_next = g_h[(t & 1) ^ 1];

        // Stage h tile [32 x 200] from L2 (bypass stale L1 with ldcg)
        for (int idx = tid; idx < 1600; idx += 256) {
            int row = idx / 50, col = idx % 50;
            float4 v = __ldcg((const float4*)&h_prev[(b0 + row) * Hsz] + col);
            ((float4*)hs)[row * 50 + col] = v;
        }
        __syncthreads();

        if (active) {
            // Prefetch pre-activations + output weight (independent of h)
            float pin[4][4];
#pragma unroll
            for (int i = 0; i < 4; i++) {
                const float* p = &g_pre[((size_t)t * Bsz + (b0 + bl + i)) * G4 + k];
                pin[i][0] = __ldg(p);        pin[i][1] = __ldg(p + 200);
                pin[i][2] = __ldg(p + 400);  pin[i][3] = __ldg(p + 600);
            }
            float wout = __ldg(&W_out[t * Hsz + k]);

            unsigned long long acc[4][4];    // packed (even-j, odd-j) partial sums
#pragma unroll
            for (int g = 0; g < 4; g++)
#pragma unroll
                for (int i = 0; i < 4; i++) acc[g][i] = 0ull;

#pragma unroll 2
            for (int q = 0; q < 50; q++) {
                ulonglong2 w0 = *(const ulonglong2*)&wq[(0 * 50 + q) * 25 + kl];
                ulonglong2 w1 = *(const ulonglong2*)&wq[(1 * 50 + q) * 25 + kl];
                ulonglong2 w2 = *(const ulonglong2*)&wq[(2 * 50 + q) * 25 + kl];
                ulonglong2 w3 = *(const ulonglong2*)&wq[(3 * 50 + q) * 25 + kl];
#pragma unroll
                for (int i = 0; i < 4; i++) {
                    ulonglong2 hv = *(const ulonglong2*)&hs[(bl + i) * Hsz + q * 4];
                    ffma2(acc[0][i], w0.x, hv.x); ffma2(acc[0][i], w0.y, hv.y);
                    ffma2(acc[1][i], w1.x, hv.x); ffma2(acc[1][i], w1.y, hv.y);
                    ffma2(acc[2][i], w2.x, hv.x); ffma2(acc[2][i], w2.y, hv.y);
                    ffma2(acc[3][i], w3.x, hv.x); ffma2(acc[3][i], w3.y, hv.y);
                }
            }

#pragma unroll
            for (int i = 0; i < 4; i++) {
                float gi = pairsum(acc[0][i]) + pin[i][0];
                float gf = pairsum(acc[1][i]) + pin[i][1];
                float gg = pairsum(acc[2][i]) + pin[i][2];
                float go = pairsum(acc[3][i]) + pin[i][3];
                gi = 1.f / (1.f + __expf(-gi));
                gf = 1.f / (1.f + __expf(-gf));
                gg = tanhf(gg);
                go = 1.f / (1.f + __expf(-go));
                float c = gf * creg[i] + gi * gg;
                creg[i] = c;
                float h = go * tanhf(c);
                h_next[(b0 + bl + i) * Hsz + k] = h;
                wacc[i] += wout * h;
            }
        }

        if (t < Tsz - 1) {
            __threadfence();          // h stores visible through L2 before arrive
            __syncthreads();
            if (tid == 0) {
                myGen++;
                unsigned prev = atomicAdd(&g_count, 1u);
                if (prev == NBLK - 1) {
                    atomicExch(&g_count, 0u);
                    __threadfence();
                    g_gen = myGen;                       // release
                } else {
                    while (g_gen < myGen) __nanosleep(64);
                }
            }
            __syncthreads();
        }
    }

    if (active) {
#pragma unroll
        for (int i = 0; i < 4; i++)
            g_part[k * Bsz + (b0 + bl + i)] = wacc[i];
    }
}

// ---------------- final reduction: out[b] = sum_k part[k][b] + b_out ----------------
__global__ __launch_bounds__(256) void finalize_kernel(const float* __restrict__ b_out,
                                                       float* __restrict__ out) {
    int b = blockIdx.x * 256 + threadIdx.x;
    if (b < Bsz) {
        float s = b_out[0];
#pragma unroll 8
        for (int k = 0; k < Hsz; k++)
            s += g_part[k * Bsz + b];
        out[b] = s;
    }
}

extern "C" void kernel_launch(void* const* d_in, const int* in_sizes, int n_in,
                              void* d_out, int out_size) {
    const float* x     = (const float*)d_in[0];
    const float* W_ih  = (const float*)d_in[1];
    const float* W_hh  = (const float*)d_in[2];
    const float* b_ih  = (const float*)d_in[3];
    const float* b_hh  = (const float*)d_in[4];
    const float* W_out = (const float*)d_in[5];
    const float* b_out = (const float*)d_in[6];
    float* out = (float*)d_out;

    // Set the smem opt-in only when NOT capturing (it is persistent, and the
    // harness always runs a correctness call before graph capture).
    cudaStreamCaptureStatus cap = cudaStreamCaptureStatusNone;
    cudaStreamIsCapturing(0, &cap);
    if (cap == cudaStreamCaptureStatusNone) {
        cudaFuncSetAttribute(lstm_persist,
                             cudaFuncAttributeMaxDynamicSharedMemorySize, SMEM_BYTES);
    }

    prep_kernel<<<400, 256>>>(b_ih, b_hh);
    pre_gemm<<<dim3(7, 2048), 256>>>(x, W_ih);
    lstm_persist<<<dim3(8, 16), 256, SMEM_BYTES>>>(W_hh, W_out);
    finalize_kernel<<<2, 256>>>(b_out, out);
}

// round 12
// speedup vs baseline: 1.4057x; 1.0205x over previous
#include <cuda_runtime.h>
#include <math.h>

#define Bsz 512
#define Tsz 512
#define Dsz 256
#define Hsz 200
#define G4  800
#define NBLK 128          // 8 k-slices x 16 batch-tiles, 1 block/SM -> co-resident

// ---------------- scratch (static device allocations) ----------------
__device__ float  g_pre[(size_t)Tsz * Bsz * G4];   // [t][b][800]
__device__ float  g_bsum[G4];                      // b_ih + b_hh
__device__ float  g_h[2][Bsz * Hsz];               // double-buffered hidden state
__device__ float  g_part[Hsz * Bsz];               // per-(k,b) output partials
__device__ unsigned g_count;                       // grid barrier arrive counter
__device__ volatile unsigned g_gen;                // grid barrier generation

// ---------------- f32x2 helpers (FFMA2: 2 MACs per instruction) ----------------
__device__ __forceinline__ void ffma2(unsigned long long &d,
                                      unsigned long long a, unsigned long long b) {
    asm("fma.rn.f32x2 %0, %1, %2, %0;" : "+l"(d) : "l"(a), "l"(b));
}
__device__ __forceinline__ float pairsum(unsigned long long v) {
    float lo, hi;
    asm("mov.b64 {%0,%1}, %2;" : "=f"(lo), "=f"(hi) : "l"(v));
    return lo + hi;
}

// ---------------- branch-free MUFU activations (err ~1e-6, saturating) ----------
__device__ __forceinline__ float fsig(float x) {
    float e, r;
    asm("ex2.approx.f32 %0, %1;" : "=f"(e) : "f"(-1.4426950408889634f * x));
    asm("rcp.approx.f32 %0, %1;" : "=f"(r) : "f"(1.f + e));
    return r;
}
__device__ __forceinline__ float ftanh(float x) {
    float e, r;
    asm("ex2.approx.f32 %0, %1;" : "=f"(e) : "f"(-2.8853900817779268f * x));
    asm("rcp.approx.f32 %0, %1;" : "=f"(r) : "f"(1.f + e));
    return fmaf(2.f, r, -1.f);
}

// ---------------- prep: zero h, fuse biases, reset barrier ----------------
__global__ __launch_bounds__(256) void prep_kernel(const float* __restrict__ b_ih,
                                                   const float* __restrict__ b_hh) {
    int i = blockIdx.x * 256 + threadIdx.x;
    if (i < Bsz * Hsz) { g_h[0][i] = 0.f; g_h[1][i] = 0.f; }
    if (i < G4) g_bsum[i] = b_ih[i] + b_hh[i];
    if (i == 0) { g_count = 0u; g_gen = 0u; }
}

// ---------------- pre-GEMM (f32x2): pre[t][b][g] = x[b][t][:].W_ih[g][:] + bsum ----------------
__global__ __launch_bounds__(256) void pre_gemm(const float* __restrict__ x,
                                                const float* __restrict__ W_ih) {
    __shared__ __align__(16) float2 As2[8][128];   // [k-pair][m] -> (x_k0, x_k1)
    __shared__ __align__(16) float2 Bs2[8][128];   // [k-pair][g]
    int tid = threadIdx.x;
    int tx = tid & 15, ty = tid >> 4;
    int m0 = blockIdx.y * 128;   // flattened (b*512+t) row
    int n0 = blockIdx.x * 128;   // gate column

    unsigned long long acc2[8][8];   // packed (even-k, odd-k) partial sums
#pragma unroll
    for (int i = 0; i < 8; i++)
#pragma unroll
        for (int j = 0; j < 8; j++) acc2[i][j] = 0ull;

    for (int k0 = 0; k0 < Dsz; k0 += 16) {
#pragma unroll
        for (int l = 0; l < 2; l++) {
            int flat = tid * 2 + l;          // 0..511
            int ml = flat >> 2;              // 0..127
            int kk = (flat & 3) << 2;        // 0,4,8,12
            int kp = kk >> 1;                // 0,2,4,6
            float4 v = *(const float4*)&x[(size_t)(m0 + ml) * Dsz + k0 + kk];
            As2[kp][ml]     = make_float2(v.x, v.y);
            As2[kp + 1][ml] = make_float2(v.z, v.w);
            int g = n0 + ml;
            float4 w = make_float4(0.f, 0.f, 0.f, 0.f);
            if (g < G4) w = *(const float4*)&W_ih[(size_t)g * Dsz + k0 + kk];
            Bs2[kp][ml]     = make_float2(w.x, w.y);
            Bs2[kp + 1][ml] = make_float2(w.z, w.w);
        }
        __syncthreads();
#pragma unroll
        for (int kp = 0; kp < 8; kp++) {
            unsigned long long a[8], b[8];
            const ulonglong2* ap = (const ulonglong2*)&As2[kp][ty * 8];
            const ulonglong2* bp = (const ulonglong2*)&Bs2[kp][tx * 8];
#pragma unroll
            for (int q = 0; q < 4; q++) {
                ulonglong2 av = ap[q]; a[q * 2] = av.x; a[q * 2 + 1] = av.y;
                ulonglong2 bv = bp[q]; b[q * 2] = bv.x; b[q * 2 + 1] = bv.y;
            }
#pragma unroll
            for (int i = 0; i < 8; i++)
#pragma unroll
                for (int j = 0; j < 8; j++)
                    ffma2(acc2[i][j], a[i], b[j]);
        }
        __syncthreads();
    }
#pragma unroll
    for (int i = 0; i < 8; i++) {
        int m = m0 + ty * 8 + i;
        int b = m >> 9;
        int t = m & 511;
        size_t base = ((size_t)t * Bsz + b) * G4;
#pragma unroll
        for (int j4 = 0; j4 < 2; j4++) {
            int g = n0 + tx * 8 + j4 * 4;
            if (g + 3 < G4) {
                float4 v;
                v.x = pairsum(acc2[i][j4 * 4 + 0]) + g_bsum[g + 0];
                v.y = pairsum(acc2[i][j4 * 4 + 1]) + g_bsum[g + 1];
                v.z = pairsum(acc2[i][j4 * 4 + 2]) + g_bsum[g + 2];
                v.w = pairsum(acc2[i][j4 * 4 + 3]) + g_bsum[g + 3];
                *(float4*)&g_pre[base + g] = v;
            }
        }
    }
}

// ---------------- persistent LSTM: all 512 steps in ONE launch ----------------
#define WQ_N (4 * 50 * 25)                 // float4 count: [g][jquad][k_local]
#define SMEM_BYTES (WQ_N * 16 + 32 * Hsz * 4)   // 80000 + 25600 = 105600

__global__ __launch_bounds__(256, 1) void lstm_persist(const float* __restrict__ W_hh,
                                                       const float* __restrict__ W_out) {
    extern __shared__ char smem[];
    float4* wq = (float4*)smem;                       // [g][q][k_local] -> (w4q..w4q+3)
    float*  hs = (float*)(smem + WQ_N * 16);          // [32 b_local][200 j]
    int tid = threadIdx.x;
    int k0 = blockIdx.x * 25;
    int b0 = blockIdx.y * 32;

    // Build weight tile once: wq[g][q][kl] = W_hh[g*200 + k0+kl][4q..4q+3]
    for (int idx = tid; idx < WQ_N; idx += 256) {
        int g  = idx / 1250;
        int r  = idx % 1250;
        int q  = r / 25;
        int kl = r % 25;
        wq[(g * 50 + q) * 25 + kl] =
            *(const float4*)&W_hh[(size_t)(g * Hsz + k0 + kl) * Hsz + q * 4];
    }

    int kl = tid % 25;
    int bg = tid / 25;          // 0..7 (tid<200), each owns 4 batch rows
    int k  = k0 + kl;
    int bl = bg * 4;
    bool active = (tid < 200);

    float creg[4] = {0.f, 0.f, 0.f, 0.f};     // cell state: registers, whole run
    float wacc[4] = {0.f, 0.f, 0.f, 0.f};     // sum_t W_out[t,k]*h[t,b,k]
    unsigned myGen = 0;
    __syncthreads();                           // wq ready

    for (int t = 0; t < Tsz; t++) {
        const float* __restrict__ h_prev = g_h[t & 1];
        float* __restrict__ h_next = g_h[(t & 1) ^ 1];

        // Stage h tile [32 x 200] from L2 (bypass stale L1 with ldcg)
        for (int idx = tid; idx < 1600; idx += 256) {
            int row = idx / 50, col = idx % 50;
            float4 v = __ldcg((const float4*)&h_prev[(b0 + row) * Hsz] + col);
            ((float4*)hs)[row * 50 + col] = v;
        }
        __syncthreads();

        if (active) {
            // Prefetch pre-activations + output weight (independent of h)
            float pin[4][4];
#pragma unroll
            for (int i = 0; i < 4; i++) {
                const float* p = &g_pre[((size_t)t * Bsz + (b0 + bl + i)) * G4 + k];
                pin[i][0] = __ldg(p);        pin[i][1] = __ldg(p + 200);
                pin[i][2] = __ldg(p + 400);  pin[i][3] = __ldg(p + 600);
            }
            float wout = __ldg(&W_out[t * Hsz + k]);

            unsigned long long acc[4][4];    // packed (even-j, odd-j) partial sums
#pragma unroll
            for (int g = 0; g < 4; g++)
#pragma unroll
                for (int i = 0; i < 4; i++) acc[g][i] = 0ull;

#pragma unroll 2
            for (int q = 0; q < 50; q++) {
                ulonglong2 w0 = *(const ulonglong2*)&wq[(0 * 50 + q) * 25 + kl];
                ulonglong2 w1 = *(const ulonglong2*)&wq[(1 * 50 + q) * 25 + kl];
                ulonglong2 w2 = *(const ulonglong2*)&wq[(2 * 50 + q) * 25 + kl];
                ulonglong2 w3 = *(const ulonglong2*)&wq[(3 * 50 + q) * 25 + kl];
#pragma unroll
                for (int i = 0; i < 4; i++) {
                    ulonglong2 hv = *(const ulonglong2*)&hs[(bl + i) * Hsz + q * 4];
                    ffma2(acc[0][i], w0.x, hv.x); ffma2(acc[0][i], w0.y, hv.y);
                    ffma2(acc[1][i], w1.x, hv.x); ffma2(acc[1][i], w1.y, hv.y);
                    ffma2(acc[2][i], w2.x, hv.x); ffma2(acc[2][i], w2.y, hv.y);
                    ffma2(acc[3][i], w3.x, hv.x); ffma2(acc[3][i], w3.y, hv.y);
                }
            }

#pragma unroll
            for (int i = 0; i < 4; i++) {
                float gi = fsig (pairsum(acc[0][i]) + pin[i][0]);
                float gf = fsig (pairsum(acc[1][i]) + pin[i][1]);
                float gg = ftanh(pairsum(acc[2][i]) + pin[i][2]);
                float go = fsig (pairsum(acc[3][i]) + pin[i][3]);
                float c = gf * creg[i] + gi * gg;
                creg[i] = c;
                float h = go * ftanh(c);
                h_next[(b0 + bl + i) * Hsz + k] = h;
                wacc[i] += wout * h;
            }
        }

        if (t < Tsz - 1) {
            __threadfence();          // h stores visible through L2 before arrive
            __syncthreads();
            if (tid == 0) {
                myGen++;
                unsigned prev = atomicAdd(&g_count, 1u);
                if (prev == NBLK - 1) {
                    atomicExch(&g_count, 0u);
                    __threadfence();
                    g_gen = myGen;                       // release
                } else {
                    while (g_gen < myGen) __nanosleep(32);
                }
            }
            __syncthreads();
        }
    }

    if (active) {
#pragma unroll
        for (int i = 0; i < 4; i++)
            g_part[k * Bsz + (b0 + bl + i)] = wacc[i];
    }
}

// ---------------- final reduction: out[b] = sum_k part[k][b] + b_out ----------------
__global__ __launch_bounds__(256) void finalize_kernel(const float* __restrict__ b_out,
                                                       float* __restrict__ out) {
    int b = blockIdx.x * 256 + threadIdx.x;
    if (b < Bsz) {
        float s = b_out[0];
#pragma unroll 8
        for (int k = 0; k < Hsz; k++)
            s += g_part[k * Bsz + b];
        out[b] = s;
    }
}

extern "C" void kernel_launch(void* const* d_in, const int* in_sizes, int n_in,
                              void* d_out, int out_size) {
    const float* x     = (const float*)d_in[0];
    const float* W_ih  = (const float*)d_in[1];
    const float* W_hh  = (const float*)d_in[2];
    const float* b_ih  = (const float*)d_in[3];
    const float* b_hh  = (const float*)d_in[4];
    const float* W_out = (const float*)d_in[5];
    const float* b_out = (const float*)d_in[6];
    float* out = (float*)d_out;

    // Set the smem opt-in only when NOT capturing (persistent; harness always
    // runs a correctness call before graph capture).
    cudaStreamCaptureStatus cap = cudaStreamCaptureStatusNone;
    cudaStreamIsCapturing(0, &cap);
    if (cap == cudaStreamCaptureStatusNone) {
        cudaFuncSetAttribute(lstm_persist,
                             cudaFuncAttributeMaxDynamicSharedMemorySize, SMEM_BYTES);
    }

    prep_kernel<<<400, 256>>>(b_ih, b_hh);
    pre_gemm<<<dim3(7, 2048), 256>>>(x, W_ih);
    lstm_persist<<<dim3(8, 16), 256, SMEM_BYTES>>>(W_hh, W_out);
    finalize_kernel<<<2, 256>>>(b_out, out);
}

// round 14
// speedup vs baseline: 1.4330x; 1.0195x over previous
#include <cuda_runtime.h>
#include <math.h>

#define Bsz 512
#define Tsz 512
#define Dsz 256
#define Hsz 200
#define G4  800
#define NGRP 16           // independent barrier groups (one per batch-tile)
#define GRP_SZ 8          // 8 k-slice blocks per group
#define BAR_PAD 64        // 256-byte spacing between group counters

// ---------------- scratch (static device allocations) ----------------
__device__ float  g_pre[(size_t)Tsz * Bsz * G4];   // [t][b][800]
__device__ float  g_bsum[G4];                      // b_ih + b_hh
__device__ float  g_h[2][Bsz * Hsz];               // double-buffered hidden state
__device__ float  g_part[Hsz * Bsz];               // per-(k,b) output partials
__device__ unsigned g_count[NGRP * BAR_PAD];       // per-group arrive counters
__device__ volatile unsigned g_gen[NGRP * BAR_PAD];// per-group generations

// ---------------- f32x2 helpers (FFMA2: 2 MACs per instruction) ----------------
__device__ __forceinline__ void ffma2(unsigned long long &d,
                                      unsigned long long a, unsigned long long b) {
    asm("fma.rn.f32x2 %0, %1, %2, %0;" : "+l"(d) : "l"(a), "l"(b));
}
__device__ __forceinline__ float pairsum(unsigned long long v) {
    float lo, hi;
    asm("mov.b64 {%0,%1}, %2;" : "=f"(lo), "=f"(hi) : "l"(v));
    return lo + hi;
}

// ---------------- branch-free MUFU activations (err ~1e-6, saturating) ----------
__device__ __forceinline__ float fsig(float x) {
    float e, r;
    asm("ex2.approx.f32 %0, %1;" : "=f"(e) : "f"(-1.4426950408889634f * x));
    asm("rcp.approx.f32 %0, %1;" : "=f"(r) : "f"(1.f + e));
    return r;
}
__device__ __forceinline__ float ftanh(float x) {
    float e, r;
    asm("ex2.approx.f32 %0, %1;" : "=f"(e) : "f"(-2.8853900817779268f * x));
    asm("rcp.approx.f32 %0, %1;" : "=f"(r) : "f"(1.f + e));
    return fmaf(2.f, r, -1.f);
}

// ---------------- prep: zero h, fuse biases, reset barriers ----------------
__global__ __launch_bounds__(256) void prep_kernel(const float* __restrict__ b_ih,
                                                   const float* __restrict__ b_hh) {
    int i = blockIdx.x * 256 + threadIdx.x;
    if (i < Bsz * Hsz) { g_h[0][i] = 0.f; g_h[1][i] = 0.f; }
    if (i < G4) g_bsum[i] = b_ih[i] + b_hh[i];
    if (i < NGRP * BAR_PAD) { g_count[i] = 0u; g_gen[i] = 0u; }
}

// ---------------- pre-GEMM (f32x2): pre[t][b][g] = x[b][t][:].W_ih[g][:] + bsum ----------------
__global__ __launch_bounds__(256) void pre_gemm(const float* __restrict__ x,
                                                const float* __restrict__ W_ih) {
    __shared__ __align__(16) float2 As2[8][128];   // [k-pair][m] -> (x_k0, x_k1)
    __shared__ __align__(16) float2 Bs2[8][128];   // [k-pair][g]
    int tid = threadIdx.x;
    int tx = tid & 15, ty = tid >> 4;
    int m0 = blockIdx.y * 128;   // flattened (b*512+t) row
    int n0 = blockIdx.x * 128;   // gate column

    unsigned long long acc2[8][8];   // packed (even-k, odd-k) partial sums
#pragma unroll
    for (int i = 0; i < 8; i++)
#pragma unroll
        for (int j = 0; j < 8; j++) acc2[i][j] = 0ull;

    for (int k0 = 0; k0 < Dsz; k0 += 16) {
#pragma unroll
        for (int l = 0; l < 2; l++) {
            int flat = tid * 2 + l;          // 0..511
            int ml = flat >> 2;              // 0..127
            int kk = (flat & 3) << 2;        // 0,4,8,12
            int kp = kk >> 1;                // 0,2,4,6
            float4 v = *(const float4*)&x[(size_t)(m0 + ml) * Dsz + k0 + kk];
            As2[kp][ml]     = make_float2(v.x, v.y);
            As2[kp + 1][ml] = make_float2(v.z, v.w);
            int g = n0 + ml;
            float4 w = make_float4(0.f, 0.f, 0.f, 0.f);
            if (g < G4) w = *(const float4*)&W_ih[(size_t)g * Dsz + k0 + kk];
            Bs2[kp][ml]     = make_float2(w.x, w.y);
            Bs2[kp + 1][ml] = make_float2(w.z, w.w);
        }
        __syncthreads();
#pragma unroll
        for (int kp = 0; kp < 8; kp++) {
            unsigned long long a[8], b[8];
            const ulonglong2* ap = (const ulonglong2*)&As2[kp][ty * 8];
            const ulonglong2* bp = (const ulonglong2*)&Bs2[kp][tx * 8];
#pragma unroll
            for (int q = 0; q < 4; q++) {
                ulonglong2 av = ap[q]; a[q * 2] = av.x; a[q * 2 + 1] = av.y;
                ulonglong2 bv = bp[q]; b[q * 2] = bv.x; b[q * 2 + 1] = bv.y;
            }
#pragma unroll
            for (int i = 0; i < 8; i++)
#pragma unroll
                for (int j = 0; j < 8; j++)
                    ffma2(acc2[i][j], a[i], b[j]);
        }
        __syncthreads();
    }
#pragma unroll
    for (int i = 0; i < 8; i++) {
        int m = m0 + ty * 8 + i;
        int b = m >> 9;
        int t = m & 511;
        size_t base = ((size_t)t * Bsz + b) * G4;
#pragma unroll
        for (int j4 = 0; j4 < 2; j4++) {
            int g = n0 + tx * 8 + j4 * 4;
            if (g + 3 < G4) {
                float4 v;
                v.x = pairsum(acc2[i][j4 * 4 + 0]) + g_bsum[g + 0];
                v.y = pairsum(acc2[i][j4 * 4 + 1]) + g_bsum[g + 1];
                v.z = pairsum(acc2[i][j4 * 4 + 2]) + g_bsum[g + 2];
                v.w = pairsum(acc2[i][j4 * 4 + 3]) + g_bsum[g + 3];
                *(float4*)&g_pre[base + g] = v;
            }
        }
    }
}

// ---------------- persistent LSTM: all 512 steps in ONE launch ----------------
// Grid (8 k-slices, 16 batch-tiles) = 128 blocks, 1/SM. Blocks sharing a batch
// tile (same blockIdx.y) form an independent 8-way barrier group: h for rows
// [32*by, 32*by+32) is produced and consumed only inside the group.
#define WQ_N (4 * 50 * 25)                 // float4 count: [g][jquad][k_local]
#define SMEM_BYTES (WQ_N * 16 + 32 * Hsz * 4)   // 80000 + 25600 = 105600

__global__ __launch_bounds__(256, 1) void lstm_persist(const float* __restrict__ W_hh,
                                                       const float* __restrict__ W_out) {
    extern __shared__ char smem[];
    float4* wq = (float4*)smem;                       // [g][q][k_local] -> (w4q..w4q+3)
    float*  hs = (float*)(smem + WQ_N * 16);          // [32 b_local][200 j]
    int tid = threadIdx.x;
    int k0 = blockIdx.x * 25;
    int b0 = blockIdx.y * 32;
    int grp = blockIdx.y * BAR_PAD;                   // this group's barrier slot

    // Build weight tile once: wq[g][q][kl] = W_hh[g*200 + k0+kl][4q..4q+3]
    for (int idx = tid; idx < WQ_N; idx += 256) {
        int g  = idx / 1250;
        int r  = idx % 1250;
        int q  = r / 25;
        int kl = r % 25;
        wq[(g * 50 + q) * 25 + kl] =
            *(const float4*)&W_hh[(size_t)(g * Hsz + k0 + kl) * Hsz + q * 4];
    }

    int kl = tid % 25;
    int bg = tid / 25;          // 0..7 (tid<200), each owns 4 batch rows
    int k  = k0 + kl;
    int bl = bg * 4;
    bool active = (tid < 200);

    float creg[4] = {0.f, 0.f, 0.f, 0.f};     // cell state: registers, whole run
    float wacc[4] = {0.f, 0.f, 0.f, 0.f};     // sum_t W_out[t,k]*h[t,b,k]
    float pin[4][4];                           // pipelined pre-activations
    float wout = 0.f;
    unsigned myGen = 0;
    __syncthreads();                           // wq ready

    // Preload pre-activations for t=0 (independent of recurrence)
    if (active) {
#pragma unroll
        for (int i = 0; i < 4; i++) {
            const float* p = &g_pre[(size_t)(b0 + bl + i) * G4 + k];
            pin[i][0] = __ldg(p);        pin[i][1] = __ldg(p + 200);
            pin[i][2] = __ldg(p + 400);  pin[i][3] = __ldg(p + 600);
        }
        wout = __ldg(&W_out[k]);
    }

    for (int t = 0; t < Tsz; t++) {
        const float* __restrict__ h_prev = g_h[t & 1];
        float* __restrict__ h_next = g_h[(t & 1) ^ 1];

        // Stage h tile [32 x 200] from L2 (bypass stale L1 with ldcg)
        for (int idx = tid; idx < 1600; idx += 256) {
            int row = idx / 50, col = idx % 50;
            float4 v = __ldcg((const float4*)&h_prev[(b0 + row) * Hsz] + col);
            ((float4*)hs)[row * 50 + col] = v;
        }
        __syncthreads();

        if (active) {
            unsigned long long acc[4][4];    // packed (even-j, odd-j) partial sums
#pragma unroll
            for (int g = 0; g < 4; g++)
#pragma unroll
                for (int i = 0; i < 4; i++) acc[g][i] = 0ull;

#pragma unroll 2
            for (int q = 0; q < 50; q++) {
                ulonglong2 w0 = *(const ulonglong2*)&wq[(0 * 50 + q) * 25 + kl];
                ulonglong2 w1 = *(const ulonglong2*)&wq[(1 * 50 + q) * 25 + kl];
                ulonglong2 w2 = *(const ulonglong2*)&wq[(2 * 50 + q) * 25 + kl];
                ulonglong2 w3 = *(const ulonglong2*)&wq[(3 * 50 + q) * 25 + kl];
#pragma unroll
                for (int i = 0; i < 4; i++) {
                    ulonglong2 hv = *(const ulonglong2*)&hs[(bl + i) * Hsz + q * 4];
                    ffma2(acc[0][i], w0.x, hv.x); ffma2(acc[0][i], w0.y, hv.y);
                    ffma2(acc[1][i], w1.x, hv.x); ffma2(acc[1][i], w1.y, hv.y);
                    ffma2(acc[2][i], w2.x, hv.x); ffma2(acc[2][i], w2.y, hv.y);
                    ffma2(acc[3][i], w3.x, hv.x); ffma2(acc[3][i], w3.y, hv.y);
                }
            }

#pragma unroll
            for (int i = 0; i < 4; i++) {
                float gi = fsig (pairsum(acc[0][i]) + pin[i][0]);
                float gf = fsig (pairsum(acc[1][i]) + pin[i][1]);
                float gg = ftanh(pairsum(acc[2][i]) + pin[i][2]);
                float go = fsig (pairsum(acc[3][i]) + pin[i][3]);
                float c = gf * creg[i] + gi * gg;
                creg[i] = c;
                float h = go * ftanh(c);
                h_next[(b0 + bl + i) * Hsz + k] = h;
                wacc[i] += wout * h;
            }
        }

        if (t < Tsz - 1) {
            __threadfence();          // h stores visible through L2 before arrive
            __syncthreads();

            // Prefetch t+1 pre-activations during the barrier-wait window
            if (active) {
#pragma unroll
                for (int i = 0; i < 4; i++) {
                    const float* p =
                        &g_pre[((size_t)(t + 1) * Bsz + (b0 + bl + i)) * G4 + k];
                    pin[i][0] = __ldg(p);        pin[i][1] = __ldg(p + 200);
                    pin[i][2] = __ldg(p + 400);  pin[i][3] = __ldg(p + 600);
                }
                wout = __ldg(&W_out[(t + 1) * Hsz + k]);
            }

            if (tid == 0) {
                myGen++;
                unsigned prev = atomicAdd(&g_count[grp], 1u);
                if (prev == GRP_SZ - 1) {
                    atomicExch(&g_count[grp], 0u);
                    __threadfence();
                    g_gen[grp] = myGen;                  // release group
                } else {
                    while (g_gen[grp] < myGen) __nanosleep(32);
                }
            }
            __syncthreads();
        }
    }

    if (active) {
#pragma unroll
        for (int i = 0; i < 4; i++)
            g_part[k * Bsz + (b0 + bl + i)] = wacc[i];
    }
}

// ---------------- final reduction: out[b] = sum_k part[k][b] + b_out ----------------
__global__ __launch_bounds__(256) void finalize_kernel(const float* __restrict__ b_out,
                                                       float* __restrict__ out) {
    int b = blockIdx.x * 256 + threadIdx.x;
    if (b < Bsz) {
        float s = b_out[0];
#pragma unroll 8
        for (int k = 0; k < Hsz; k++)
            s += g_part[k * Bsz + b];
        out[b] = s;
    }
}

extern "C" void kernel_launch(void* const* d_in, const int* in_sizes, int n_in,
                              void* d_out, int out_size) {
    const float* x     = (const float*)d_in[0];
    const float* W_ih  = (const float*)d_in[1];
    const float* W_hh  = (const float*)d_in[2];
    const float* b_ih  = (const float*)d_in[3];
    const float* b_hh  = (const float*)d_in[4];
    const float* W_out = (const float*)d_in[5];
    const float* b_out = (const float*)d_in[6];
    float* out = (float*)d_out;

    // Set the smem opt-in only when NOT capturing (persistent; harness always
    // runs a correctness call before graph capture).
    cudaStreamCaptureStatus cap = cudaStreamCaptureStatusNone;
    cudaStreamIsCapturing(0, &cap);
    if (cap == cudaStreamCaptureStatusNone) {
        cudaFuncSetAttribute(lstm_persist,
                             cudaFuncAttributeMaxDynamicSharedMemorySize, SMEM_BYTES);
    }

    prep_kernel<<<400, 256>>>(b_ih, b_hh);
    pre_gemm<<<dim3(7, 2048), 256>>>(x, W_ih);
    lstm_persist<<<dim3(8, 16), 256, SMEM_BYTES>>>(W_hh, W_out);
    finalize_kernel<<<2, 256>>>(b_out, out);
}

// round 15
// speedup vs baseline: 1.4852x; 1.0364x over previous
#include <cuda_runtime.h>
#include <math.h>

#define Bsz 512
#define Tsz 512
#define Dsz 256
#define Hsz 200
#define G4  800
#define NGRP 16           // independent barrier groups (one per batch-tile)
#define GRP_SZ 8          // 8 k-slice blocks per group
#define BAR_PAD 64        // 256-byte spacing between group counters

// ---------------- scratch (static device allocations) ----------------
__device__ float  g_pre[(size_t)Tsz * Bsz * G4];   // [t][b][800]
__device__ float  g_bsum[G4];                      // b_ih + b_hh
__device__ float  g_h[2][Bsz * Hsz];               // double-buffered hidden state
__device__ float  g_part[Hsz * Bsz];               // per-(k,b) output partials
__device__ unsigned g_count[NGRP * BAR_PAD];       // per-group arrive counters
__device__ volatile unsigned g_gen[NGRP * BAR_PAD];// per-group generations

// ---------------- f32x2 helpers (FFMA2: 2 MACs per instruction) ----------------
__device__ __forceinline__ void ffma2(unsigned long long &d,
                                      unsigned long long a, unsigned long long b) {
    asm("fma.rn.f32x2 %0, %1, %2, %0;" : "+l"(d) : "l"(a), "l"(b));
}
__device__ __forceinline__ float pairsum(unsigned long long v) {
    float lo, hi;
    asm("mov.b64 {%0,%1}, %2;" : "=f"(lo), "=f"(hi) : "l"(v));
    return lo + hi;
}

// ---------------- branch-free MUFU activations (err ~1e-6, saturating) ----------
__device__ __forceinline__ float fsig(float x) {
    float e, r;
    asm("ex2.approx.f32 %0, %1;" : "=f"(e) : "f"(-1.4426950408889634f * x));
    asm("rcp.approx.f32 %0, %1;" : "=f"(r) : "f"(1.f + e));
    return r;
}
__device__ __forceinline__ float ftanh(float x) {
    float e, r;
    asm("ex2.approx.f32 %0, %1;" : "=f"(e) : "f"(-2.8853900817779268f * x));
    asm("rcp.approx.f32 %0, %1;" : "=f"(r) : "f"(1.f + e));
    return fmaf(2.f, r, -1.f);
}

// ---------------- prep: zero h, fuse biases, reset barriers ----------------
__global__ __launch_bounds__(256) void prep_kernel(const float* __restrict__ b_ih,
                                                   const float* __restrict__ b_hh) {
    int i = blockIdx.x * 256 + threadIdx.x;
    if (i < Bsz * Hsz) { g_h[0][i] = 0.f; g_h[1][i] = 0.f; }
    if (i < G4) g_bsum[i] = b_ih[i] + b_hh[i];
    if (i < NGRP * BAR_PAD) { g_count[i] = 0u; g_gen[i] = 0u; }
}

// ---------------- pre-GEMM (f32x2): pre[t][b][g] = x[b][t][:].W_ih[g][:] + bsum ----------------
__global__ __launch_bounds__(256) void pre_gemm(const float* __restrict__ x,
                                                const float* __restrict__ W_ih) {
    __shared__ __align__(16) float2 As2[8][128];   // [k-pair][m] -> (x_k0, x_k1)
    __shared__ __align__(16) float2 Bs2[8][128];   // [k-pair][g]
    int tid = threadIdx.x;
    int tx = tid & 15, ty = tid >> 4;
    int m0 = blockIdx.y * 128;   // flattened (b*512+t) row
    int n0 = blockIdx.x * 128;   // gate column

    unsigned long long acc2[8][8];   // packed (even-k, odd-k) partial sums
#pragma unroll
    for (int i = 0; i < 8; i++)
#pragma unroll
        for (int j = 0; j < 8; j++) acc2[i][j] = 0ull;

    for (int k0 = 0; k0 < Dsz; k0 += 16) {
#pragma unroll
        for (int l = 0; l < 2; l++) {
            int flat = tid * 2 + l;          // 0..511
            int ml = flat >> 2;              // 0..127
            int kk = (flat & 3) << 2;        // 0,4,8,12
            int kp = kk >> 1;                // 0,2,4,6
            float4 v = *(const float4*)&x[(size_t)(m0 + ml) * Dsz + k0 + kk];
            As2[kp][ml]     = make_float2(v.x, v.y);
            As2[kp + 1][ml] = make_float2(v.z, v.w);
            int g = n0 + ml;
            float4 w = make_float4(0.f, 0.f, 0.f, 0.f);
            if (g < G4) w = *(const float4*)&W_ih[(size_t)g * Dsz + k0 + kk];
            Bs2[kp][ml]     = make_float2(w.x, w.y);
            Bs2[kp + 1][ml] = make_float2(w.z, w.w);
        }
        __syncthreads();
#pragma unroll
        for (int kp = 0; kp < 8; kp++) {
            unsigned long long a[8], b[8];
            const ulonglong2* ap = (const ulonglong2*)&As2[kp][ty * 8];
            const ulonglong2* bp = (const ulonglong2*)&Bs2[kp][tx * 8];
#pragma unroll
            for (int q = 0; q < 4; q++) {
                ulonglong2 av = ap[q]; a[q * 2] = av.x; a[q * 2 + 1] = av.y;
                ulonglong2 bv = bp[q]; b[q * 2] = bv.x; b[q * 2 + 1] = bv.y;
            }
#pragma unroll
            for (int i = 0; i < 8; i++)
#pragma unroll
                for (int j = 0; j < 8; j++)
                    ffma2(acc2[i][j], a[i], b[j]);
        }
        __syncthreads();
    }
#pragma unroll
    for (int i = 0; i < 8; i++) {
        int m = m0 + ty * 8 + i;
        int b = m >> 9;
        int t = m & 511;
        size_t base = ((size_t)t * Bsz + b) * G4;
#pragma unroll
        for (int j4 = 0; j4 < 2; j4++) {
            int g = n0 + tx * 8 + j4 * 4;
            if (g + 3 < G4) {
                float4 v;
                v.x = pairsum(acc2[i][j4 * 4 + 0]) + g_bsum[g + 0];
                v.y = pairsum(acc2[i][j4 * 4 + 1]) + g_bsum[g + 1];
                v.z = pairsum(acc2[i][j4 * 4 + 2]) + g_bsum[g + 2];
                v.w = pairsum(acc2[i][j4 * 4 + 3]) + g_bsum[g + 3];
                *(float4*)&g_pre[base + g] = v;
            }
        }
    }
}

// ---------------- persistent LSTM: all 512 steps in ONE launch ----------------
// Grid (8 k-slices, 16 batch-tiles) = 128 blocks, 1/SM. Blocks sharing a batch
// tile (same blockIdx.y) form an independent 8-way barrier group.
// Thread map is bg-MAJOR: warp w owns batch rows [4w, 4w+4), lane l owns k0+l
// (lanes 25-31 idle). hv smem reads are lane-uniform broadcasts (no conflicts);
// weight reads are lane-consecutive float4 (conflict-free).
#define WQ_N (4 * 50 * 25)                 // float4 count: [g][jquad][k_local]
#define SMEM_BYTES (WQ_N * 16 + 32 * Hsz * 4)   // 80000 + 25600 = 105600

__global__ __launch_bounds__(256, 1) void lstm_persist(const float* __restrict__ W_hh,
                                                       const float* __restrict__ W_out) {
    extern __shared__ char smem[];
    float4* wq = (float4*)smem;                       // [g][q][k_local] -> (w4q..w4q+3)
    float*  hs = (float*)(smem + WQ_N * 16);          // [32 b_local][200 j]
    int tid = threadIdx.x;
    int k0 = blockIdx.x * 25;
    int b0 = blockIdx.y * 32;
    int grp = blockIdx.y * BAR_PAD;                   // this group's barrier slot

    // Build weight tile once: wq[g][q][kl] = W_hh[g*200 + k0+kl][4q..4q+3]
    for (int idx = tid; idx < WQ_N; idx += 256) {
        int g  = idx / 1250;
        int r  = idx % 1250;
        int q  = r / 25;
        int kl = r % 25;
        wq[(g * 50 + q) * 25 + kl] =
            *(const float4*)&W_hh[(size_t)(g * Hsz + k0 + kl) * Hsz + q * 4];
    }

    int kl = tid & 31;          // lane -> k index (lanes 25-31 idle)
    int bg = tid >> 5;          // warp -> batch group, each owns 4 batch rows
    int k  = k0 + kl;
    int bl = bg * 4;
    bool active = (kl < 25);

    float creg[4] = {0.f, 0.f, 0.f, 0.f};     // cell state: registers, whole run
    float wacc[4] = {0.f, 0.f, 0.f, 0.f};     // sum_t W_out[t,k]*h[t,b,k]
    float pin[4][4];                           // pipelined pre-activations
    float wout = 0.f;
    unsigned myGen = 0;
    __syncthreads();                           // wq ready

    // Preload pre-activations for t=0 (independent of recurrence)
    if (active) {
#pragma unroll
        for (int i = 0; i < 4; i++) {
            const float* p = &g_pre[(size_t)(b0 + bl + i) * G4 + k];
            pin[i][0] = __ldg(p);        pin[i][1] = __ldg(p + 200);
            pin[i][2] = __ldg(p + 400);  pin[i][3] = __ldg(p + 600);
        }
        wout = __ldg(&W_out[k]);
    }

    for (int t = 0; t < Tsz; t++) {
        const float* __restrict__ h_prev = g_h[t & 1];
        float* __restrict__ h_next = g_h[(t & 1) ^ 1];

        // Stage h tile [32 x 200] from L2 (bypass stale L1 with ldcg)
        for (int idx = tid; idx < 1600; idx += 256) {
            int row = idx / 50, col = idx % 50;
            float4 v = __ldcg((const float4*)&h_prev[(b0 + row) * Hsz] + col);
            ((float4*)hs)[row * 50 + col] = v;
        }
        __syncthreads();

        if (active) {
            unsigned long long acc[4][4];    // packed (even-j, odd-j) partial sums
#pragma unroll
            for (int g = 0; g < 4; g++)
#pragma unroll
                for (int i = 0; i < 4; i++) acc[g][i] = 0ull;

#pragma unroll 2
            for (int q = 0; q < 50; q++) {
                ulonglong2 w0 = *(const ulonglong2*)&wq[(0 * 50 + q) * 25 + kl];
                ulonglong2 w1 = *(const ulonglong2*)&wq[(1 * 50 + q) * 25 + kl];
                ulonglong2 w2 = *(const ulonglong2*)&wq[(2 * 50 + q) * 25 + kl];
                ulonglong2 w3 = *(const ulonglong2*)&wq[(3 * 50 + q) * 25 + kl];
#pragma unroll
                for (int i = 0; i < 4; i++) {
                    ulonglong2 hv = *(const ulonglong2*)&hs[(bl + i) * Hsz + q * 4];
                    ffma2(acc[0][i], w0.x, hv.x); ffma2(acc[0][i], w0.y, hv.y);
                    ffma2(acc[1][i], w1.x, hv.x); ffma2(acc[1][i], w1.y, hv.y);
                    ffma2(acc[2][i], w2.x, hv.x); ffma2(acc[2][i], w2.y, hv.y);
                    ffma2(acc[3][i], w3.x, hv.x); ffma2(acc[3][i], w3.y, hv.y);
                }
            }

#pragma unroll
            for (int i = 0; i < 4; i++) {
                float gi = fsig (pairsum(acc[0][i]) + pin[i][0]);
                float gf = fsig (pairsum(acc[1][i]) + pin[i][1]);
                float gg = ftanh(pairsum(acc[2][i]) + pin[i][2]);
                float go = fsig (pairsum(acc[3][i]) + pin[i][3]);
                float c = gf * creg[i] + gi * gg;
                creg[i] = c;
                float h = go * ftanh(c);
                h_next[(b0 + bl + i) * Hsz + k] = h;
                wacc[i] += wout * h;
            }
        }

        if (t < Tsz - 1) {
            __threadfence();          // h stores visible through L2 before arrive
            __syncthreads();

            // Prefetch t+1 pre-activations during the barrier-wait window
            if (active) {
#pragma unroll
                for (int i = 0; i < 4; i++) {
                    const float* p =
                        &g_pre[((size_t)(t + 1) * Bsz + (b0 + bl + i)) * G4 + k];
                    pin[i][0] = __ldg(p);        pin[i][1] = __ldg(p + 200);
                    pin[i][2] = __ldg(p + 400);  pin[i][3] = __ldg(p + 600);
                }
                wout = __ldg(&W_out[(t + 1) * Hsz + k]);
            }

            if (tid == 0) {
                myGen++;
                unsigned prev = atomicAdd(&g_count[grp], 1u);
                if (prev == GRP_SZ - 1) {
                    atomicExch(&g_count[grp], 0u);
                    __threadfence();
                    g_gen[grp] = myGen;                  // release group
                } else {
                    while (g_gen[grp] < myGen) __nanosleep(32);
                }
            }
            __syncthreads();
        }
    }

    if (active) {
#pragma unroll
        for (int i = 0; i < 4; i++)
            g_part[k * Bsz + (b0 + bl + i)] = wacc[i];
    }
}

// ---------------- final reduction: out[b] = sum_k part[k][b] + b_out ----------------
__global__ __launch_bounds__(256) void finalize_kernel(const float* __restrict__ b_out,
                                                       float* __restrict__ out) {
    int b = blockIdx.x * 256 + threadIdx.x;
    if (b < Bsz) {
        float s = b_out[0];
#pragma unroll 8
        for (int k = 0; k < Hsz; k++)
            s += g_part[k * Bsz + b];
        out[b] = s;
    }
}

extern "C" void kernel_launch(void* const* d_in, const int* in_sizes, int n_in,
                              void* d_out, int out_size) {
    const float* x     = (const float*)d_in[0];
    const float* W_ih  = (const float*)d_in[1];
    const float* W_hh  = (const float*)d_in[2];
    const float* b_ih  = (const float*)d_in[3];
    const float* b_hh  = (const float*)d_in[4];
    const float* W_out = (const float*)d_in[5];
    const float* b_out = (const float*)d_in[6];
    float* out = (float*)d_out;

    // Set the smem opt-in only when NOT capturing (persistent; harness always
    // runs a correctness call before graph capture).
    cudaStreamCaptureStatus cap = cudaStreamCaptureStatusNone;
    cudaStreamIsCapturing(0, &cap);
    if (cap == cudaStreamCaptureStatusNone) {
        cudaFuncSetAttribute(lstm_persist,
                             cudaFuncAttributeMaxDynamicSharedMemorySize, SMEM_BYTES);
    }

    prep_kernel<<<400, 256>>>(b_ih, b_hh);
    pre_gemm<<<dim3(7, 2048), 256>>>(x, W_ih);
    lstm_persist<<<dim3(8, 16), 256, SMEM_BYTES>>>(W_hh, W_out);
    finalize_kernel<<<2, 256>>>(b_out, out);
}